// round 11
// baseline (speedup 1.0000x reference)
#include <cuda_runtime.h>
#include <cuda_bf16.h>
#include <math.h>
#include <stdint.h>

// Problem constants
#define B_  64
#define T_  32
#define S_  33
#define V_  32000
#define E_  512
#define H_  1024
#define G4  4096
#define M1  (S_*B_)       // 2112

// recurrence config
#define NCTA  128
#define NTT   256         // 8 warps
#define NKS   64
#define CHUNK_ROWS 128
#define NCHUNK (H_/CHUNK_ROWS)   // 8
#define BSROW  144
#define CHUNK_BYTES (CHUNK_ROWS*BSROW)   // 18432
#define NSLOT  4
#define HBUF_BYTES (NSLOT*2*CHUNK_BYTES) // 147456
#define RQS    66
#define SMEM_C_OFF HBUF_BYTES
#define SMEM_TOTAL (HBUF_BYTES + 2048)   // 149504

// distributed barrier: 8 counters on separate 128B lines
#define NBARW 8

// packs
#define PACK2_U32 (NCTA*2*NKS*32*4)
#define XTILES    (M1/16)
#define XA_U32    (XTILES*32*32*4)
#define WIH_U32   (512*32*32*2)

// ---------------- device scratch ----------------
__device__ float g_xg2[M1 * G4];             // [t][gate*1024+cell][batch]
__device__ uint32_t g_wpA2_hi[PACK2_U32];
__device__ uint32_t g_wpA2_lo[PACK2_U32];
__device__ uint32_t g_xA_hi[XA_U32];
__device__ uint32_t g_xA_lo[XA_U32];
__device__ uint32_t g_wihB_hi[WIH_U32];
__device__ uint32_t g_wihB_lo[WIH_U32];
__device__ __nv_bfloat16 g_hT_hi[2][H_ * B_];   // double-buffered [cell][batch]
__device__ __nv_bfloat16 g_hT_lo[2][H_ * B_];
__device__ __align__(128) unsigned g_barw[NBARW][32];  // one counter per 128B line

__device__ __forceinline__ float sigf(float x) {
    return 1.0f / (1.0f + __expf(-x));
}
__device__ __forceinline__ float tanhfast(float x) {
    return 2.0f / (1.0f + __expf(-2.0f * x)) - 1.0f;
}
__device__ __forceinline__ void mma_bf16(float* d, uint32_t a0, uint32_t a1,
                                         uint32_t a2, uint32_t a3,
                                         uint32_t b0, uint32_t b1) {
    asm volatile(
        "mma.sync.aligned.m16n8k16.row.col.f32.bf16.bf16.f32 "
        "{%0,%1,%2,%3}, {%4,%5,%6,%7}, {%8,%9}, {%0,%1,%2,%3};"
        : "+f"(d[0]), "+f"(d[1]), "+f"(d[2]), "+f"(d[3])
        : "r"(a0), "r"(a1), "r"(a2), "r"(a3), "r"(b0), "r"(b1));
}
__device__ __forceinline__ uint32_t pack_hi(float v0, float v1,
                                            float& l0, float& l1) {
    __nv_bfloat16 h0 = __float2bfloat16(v0);
    __nv_bfloat16 h1 = __float2bfloat16(v1);
    l0 = v0 - __bfloat162float(h0);
    l1 = v1 - __bfloat162float(h1);
    return (uint32_t)__bfloat16_as_ushort(h0)
         | ((uint32_t)__bfloat16_as_ushort(h1) << 16);
}
__device__ __forceinline__ uint32_t pack_bf2(float v0, float v1) {
    return (uint32_t)__bfloat16_as_ushort(__float2bfloat16(v0))
         | ((uint32_t)__bfloat16_as_ushort(__float2bfloat16(v1)) << 16);
}
__device__ __forceinline__ uint32_t smem_u32p(const void* p) {
    uint32_t a;
    asm("{ .reg .u64 t; cvta.to.shared.u64 t, %1; cvt.u32.u64 %0, t; }"
        : "=r"(a) : "l"(p));
    return a;
}
__device__ __forceinline__ void cp16(uint32_t sdst, const void* gsrc) {
    asm volatile("cp.async.cg.shared.global [%0], [%1], 16;"
                 :: "r"(sdst), "l"(gsrc) : "memory");
}
__device__ __forceinline__ void ldsm_x2_t(uint32_t& r0, uint32_t& r1,
                                          uint32_t addr) {
    asm volatile("ldmatrix.sync.aligned.m8n8.x2.trans.shared.b16 {%0,%1}, [%2];"
                 : "=r"(r0), "=r"(r1) : "r"(addr));
}
__device__ __forceinline__ unsigned ld_acq(const unsigned* p) {
    unsigned v;
    asm volatile("ld.acquire.gpu.u32 %0, [%1];" : "=r"(v) : "l"(p));
    return v;
}

// ---------------------------------------------------------------------------
// 0a) Pack w_hh into A-frag order (rows q = gate*8+cell), proven
// ---------------------------------------------------------------------------
__global__ void prep_wpack2(const float* __restrict__ w_hh) {
    int idx = blockIdx.x * 256 + threadIdx.x;
    if (idx >= PACK2_U32) return;
    int r    = idx & 3;
    int lane = (idx >> 2) & 31;
    int ks   = (idx >> 7) & 63;
    int mi   = (idx >> 13) & 1;
    int nt   = idx >> 14;
    int row16 = (lane >> 2) + ((r & 1) << 3);
    int colp  = (lane & 3) * 2 + ((r >> 1) << 3);
    int q = mi * 16 + row16;
    int gate = q >> 3, cl = q & 7;
    const float* src = w_hh + (size_t)(gate * H_ + nt * 8 + cl) * H_ + ks * 16 + colp;
    float v0 = src[0], v1 = src[1], l0, l1;
    g_wpA2_hi[idx] = pack_hi(v0, v1, l0, l1);
    g_wpA2_lo[idx] = pack_bf2(l0, l1);
}

// 0b) Pack w_ih into B-frag order (proven)
__global__ void prep_wih(const float* __restrict__ w_ih) {
    int idx = blockIdx.x * 256 + threadIdx.x;
    if (idx >= WIH_U32) return;
    int r    = idx & 1;
    int lane = (idx >> 1) & 31;
    int ks   = (idx >> 6) & 31;
    int n8   = idx >> 11;
    int n = n8 * 8 + (lane >> 2);
    int k = ks * 16 + (lane & 3) * 2 + r * 8;
    const float* src = w_ih + (size_t)n * E_ + k;
    float v0 = src[0], v1 = src[1], l0, l1;
    g_wihB_hi[idx] = pack_hi(v0, v1, l0, l1);
    g_wihB_lo[idx] = pack_bf2(l0, l1);
}

// 0c) Build x in A-frag order (proven)
__global__ void build_x_pack(const float* __restrict__ features,
                             const int*   __restrict__ captions,
                             const float* __restrict__ W_embed,
                             const float* __restrict__ b_embed) {
    int idx = blockIdx.x * 256 + threadIdx.x;
    if (idx >= XA_U32) return;
    int rr   = idx & 3;
    int lane = (idx >> 2) & 31;
    int ks   = (idx >> 7) & 31;
    int mt   = idx >> 12;
    int row16 = (lane >> 2) + ((rr & 1) << 3);
    int colp  = (lane & 3) * 2 + ((rr >> 1) << 3);
    int m = mt * 16 + row16;
    int k = ks * 16 + colp;
    int t = m >> 6, b = m & 63;
    float v0, v1;
    if (t == 0) {
        v0 = features[b * E_ + k];
        v1 = features[b * E_ + k + 1];
    } else {
        int cap = captions[b * T_ + (t - 1)];
        v0 = W_embed[(size_t)k * V_ + cap] + b_embed[k];
        v1 = W_embed[(size_t)(k + 1) * V_ + cap] + b_embed[k + 1];
    }
    float l0, l1;
    g_xA_hi[idx] = pack_hi(v0, v1, l0, l1);
    g_xA_lo[idx] = pack_bf2(l0, l1);
}

// 0d) Init h buf 0, transposed [cell][batch]
__global__ void init_h_kernel(const float* __restrict__ h0) {
    int idx = blockIdx.x * 256 + threadIdx.x;
    if (idx >= B_ * H_) return;
    int cell = idx >> 6;
    int b    = idx & 63;
    float v = h0[b * H_ + cell];
    __nv_bfloat16 hi = __float2bfloat16(v);
    g_hT_hi[0][idx] = hi;
    g_hT_lo[0][idx] = __float2bfloat16(v - __bfloat162float(hi));
}

// ---------------------------------------------------------------------------
// 1) xg2[t][n][b] = x @ w_ih^T + bias (proven R8)
// ---------------------------------------------------------------------------
__global__ __launch_bounds__(NTT, 1)
void gemm_xg_bf16(const float* __restrict__ b_ih,
                  const float* __restrict__ b_hh,
                  float* __restrict__ C) {
    const int tid  = threadIdx.x;
    const int wid  = tid >> 5;
    const int lane = tid & 31;
    const int wm   = wid & 1;
    const int wn   = wid >> 1;
    const int tt   = blockIdx.x;
    const int mt0  = tt * 4 + wm * 2;
    const int n8_0 = blockIdx.y * 16 + wn * 4;
    const int g    = lane >> 2;
    const int tig  = lane & 3;

    const uint4* aH = (const uint4*)g_xA_hi;
    const uint4* aL = (const uint4*)g_xA_lo;
    const uint2* bH = (const uint2*)g_wihB_hi;
    const uint2* bL = (const uint2*)g_wihB_lo;

    float acc[2][4][4];
#pragma unroll
    for (int i = 0; i < 2; i++)
#pragma unroll
        for (int j = 0; j < 4; j++)
#pragma unroll
            for (int c = 0; c < 4; c++) acc[i][j][c] = 0.0f;

#pragma unroll 4
    for (int ks = 0; ks < 32; ks++) {
        uint4 ah[2], al[2];
#pragma unroll
        for (int mi = 0; mi < 2; mi++) {
            size_t ai = ((size_t)(mt0 + mi) * 32 + ks) * 32 + lane;
            ah[mi] = __ldg(&aH[ai]);
            al[mi] = __ldg(&aL[ai]);
        }
        uint2 bh[4], bl[4];
#pragma unroll
        for (int j = 0; j < 4; j++) {
            size_t bix = ((size_t)(n8_0 + j) * 32 + ks) * 32 + lane;
            bh[j] = __ldg(&bH[bix]);
            bl[j] = __ldg(&bL[bix]);
        }
#pragma unroll
        for (int j = 0; j < 4; j++) {
#pragma unroll
            for (int mi = 0; mi < 2; mi++) {
                mma_bf16(acc[mi][j], ah[mi].x, ah[mi].y, ah[mi].z, ah[mi].w,
                         bh[j].x, bh[j].y);
                mma_bf16(acc[mi][j], ah[mi].x, ah[mi].y, ah[mi].z, ah[mi].w,
                         bl[j].x, bl[j].y);
                mma_bf16(acc[mi][j], al[mi].x, al[mi].y, al[mi].z, al[mi].w,
                         bh[j].x, bh[j].y);
            }
        }
    }

#pragma unroll
    for (int j = 0; j < 4; j++) {
        int n = (n8_0 + j) * 8 + tig * 2;
        float bx = b_ih[n] + b_hh[n];
        float by = b_ih[n + 1] + b_hh[n + 1];
        float* c0p = C + ((size_t)tt * G4 + n) * 64;
        float* c1p = C + ((size_t)tt * G4 + n + 1) * 64;
#pragma unroll
        for (int mi = 0; mi < 2; mi++) {
            int b = (wm * 2 + mi) * 16 + g;
            c0p[b]     = acc[mi][j][0] + bx;
            c1p[b]     = acc[mi][j][1] + by;
            c0p[b + 8] = acc[mi][j][2] + bx;
            c1p[b + 8] = acc[mi][j][3] + by;
        }
    }
}

// ---------------------------------------------------------------------------
// helper: stage one 128-row chunk (hi+lo) into smem slot via cp.async
// ---------------------------------------------------------------------------
__device__ __forceinline__ void stage_chunk(uint32_t sbase, int slot,
                                            const __nv_bfloat16* hi,
                                            const __nv_bfloat16* lo,
                                            int c, int tid) {
#pragma unroll
    for (int i = 0; i < 8; i++) {
        int lin = i * NTT + tid;
        int mat = lin >> 10;
        int within = lin & 1023;
        int row = within >> 3;
        int col = within & 7;
        const uint4* gsrc = ((const uint4*)(mat ? lo : hi))
            + (size_t)(c * CHUNK_ROWS + row) * 8 + col;
        cp16(sbase + (slot * 2 + mat) * CHUNK_BYTES + row * BSROW + col * 16,
             gsrc);
    }
    asm volatile("cp.async.commit_group;" ::: "memory");
}

// ---------------------------------------------------------------------------
// 2) Persistent recurrence v6: R10 core + distributed 8-way barrier arrival
//    (128B-padded counter lines; 16 contenders per line instead of 128).
// ---------------------------------------------------------------------------
__global__ __launch_bounds__(NTT, 1)
void rnn_persistent6(const float* __restrict__ c0,
                     float* __restrict__ out) {
    extern __shared__ char smem[];
    const uint32_t sbase = smem_u32p(smem);
    float* red  = (float*)smem;                      // overlays staging slots
    float* c_sm = (float*)(smem + SMEM_C_OFF);

    const int tid  = threadIdx.x;
    const int lane = tid & 31;
    const int w    = tid >> 5;          // warp owns ks = 8c + w
    const int nt   = blockIdx.x;
    const int g    = lane >> 2;
    const int tig  = lane & 3;
    const int myW  = nt & (NBARW - 1);  // this CTA's barrier word

    // ---- load ALL A fragments into registers (reused for all 33 steps) ----
    uint4 aH0r[NCHUNK], aH1r[NCHUNK], aL0r[NCHUNK], aL1r[NCHUNK];
    {
        const uint4* aH0 = (const uint4*)g_wpA2_hi + ((size_t)(nt * 2 + 0) * NKS) * 32 + lane;
        const uint4* aH1 = (const uint4*)g_wpA2_hi + ((size_t)(nt * 2 + 1) * NKS) * 32 + lane;
        const uint4* aL0 = (const uint4*)g_wpA2_lo + ((size_t)(nt * 2 + 0) * NKS) * 32 + lane;
        const uint4* aL1 = (const uint4*)g_wpA2_lo + ((size_t)(nt * 2 + 1) * NKS) * 32 + lane;
#pragma unroll
        for (int c = 0; c < NCHUNK; c++) {
            int ks = c * 8 + w;
            aH0r[c] = __ldg(aH0 + (size_t)ks * 32);
            aH1r[c] = __ldg(aH1 + (size_t)ks * 32);
            aL0r[c] = __ldg(aL0 + (size_t)ks * 32);
            aL1r[c] = __ldg(aL1 + (size_t)ks * 32);
        }
    }

    const uint32_t lmRow = (uint32_t)((w * 16 + (lane & 15)) * BSROW);

    const int cl  = tid >> 5;
    const int b0e = (tid & 31) * 2;
    const int cell = nt * 8 + cl;

    c_sm[cl * 64 + b0e]     = c0[b0e * H_ + cell];
    c_sm[cl * 64 + b0e + 1] = c0[(b0e + 1) * H_ + cell];
    __syncthreads();

    for (int t = 0; t < S_; t++) {
        const int rb = t & 1;
        const int wb = (t + 1) & 1;
        const __nv_bfloat16* hiSrc = g_hT_hi[rb];
        const __nv_bfloat16* loSrc = g_hT_lo[rb];

        // prefetch xg gate values (off the critical path)
        float2 xp[4];
#pragma unroll
        for (int gate = 0; gate < 4; gate++)
            xp[gate] = __ldg((const float2*)
                &g_xg2[((size_t)t * G4 + gate * H_ + cell) * 64 + b0e]);

        float acc[2][NCHUNK][4];
#pragma unroll
        for (int i = 0; i < 2; i++)
#pragma unroll
            for (int j = 0; j < NCHUNK; j++)
#pragma unroll
                for (int c = 0; c < 4; c++) acc[i][j][c] = 0.0f;

        // prologue: stage chunks 0,1
        stage_chunk(sbase, 0, hiSrc, loSrc, 0, tid);
        stage_chunk(sbase, 1, hiSrc, loSrc, 1, tid);

#pragma unroll
        for (int c = 0; c < NCHUNK; c++) {
            if (c + 2 < NCHUNK)
                stage_chunk(sbase, (c + 2) & 3, hiSrc, loSrc, c + 2, tid);
            if (c < NCHUNK - 2)
                asm volatile("cp.async.wait_group 2;" ::: "memory");
            else if (c == NCHUNK - 2)
                asm volatile("cp.async.wait_group 1;" ::: "memory");
            else
                asm volatile("cp.async.wait_group 0;" ::: "memory");
            __syncthreads();   // single sync per chunk (slot reuse distance 4)

            const int slot = c & 3;
            const uint32_t bHbase = sbase + (slot * 2 + 0) * CHUNK_BYTES + lmRow;
            const uint32_t bLbase = sbase + (slot * 2 + 1) * CHUNK_BYTES + lmRow;

            uint32_t bh[8][2], bl[8][2];
#pragma unroll
            for (int j = 0; j < 8; j++) {
                ldsm_x2_t(bh[j][0], bh[j][1], bHbase + j * 16);
                ldsm_x2_t(bl[j][0], bl[j][1], bLbase + j * 16);
            }
#pragma unroll
            for (int j = 0; j < 8; j++) {
                mma_bf16(acc[0][j], aH0r[c].x, aH0r[c].y, aH0r[c].z, aH0r[c].w,
                         bh[j][0], bh[j][1]);
                mma_bf16(acc[1][j], aH1r[c].x, aH1r[c].y, aH1r[c].z, aH1r[c].w,
                         bh[j][0], bh[j][1]);
                mma_bf16(acc[0][j], aH0r[c].x, aH0r[c].y, aH0r[c].z, aH0r[c].w,
                         bl[j][0], bl[j][1]);
                mma_bf16(acc[1][j], aH1r[c].x, aH1r[c].y, aH1r[c].z, aH1r[c].w,
                         bl[j][0], bl[j][1]);
                mma_bf16(acc[0][j], aL0r[c].x, aL0r[c].y, aL0r[c].z, aL0r[c].w,
                         bh[j][0], bh[j][1]);
                mma_bf16(acc[1][j], aL1r[c].x, aL1r[c].y, aL1r[c].z, aL1r[c].w,
                         bh[j][0], bh[j][1]);
            }
        }
        __syncthreads();   // all ldsm reads done before red overlays slots

        // cross-warp reduce (overlays staging slots)
#pragma unroll
        for (int mi = 0; mi < 2; mi++) {
            int q = mi * 16 + g;
#pragma unroll
            for (int j = 0; j < 8; j++) {
                int col = j * 8 + tig * 2;
                *(float2*)&red[(size_t)(w * 32 + q) * RQS + col] =
                    make_float2(acc[mi][j][0], acc[mi][j][1]);
                *(float2*)&red[(size_t)(w * 32 + q + 8) * RQS + col] =
                    make_float2(acc[mi][j][2], acc[mi][j][3]);
            }
        }
        __syncthreads();

        // fused LSTM epilogue
        {
            float2 gv[4];
#pragma unroll
            for (int gate = 0; gate < 4; gate++) {
                int q = gate * 8 + cl;
                float2 s = xp[gate];
#pragma unroll
                for (int ww = 0; ww < 8; ww++) {
                    float2 p = *(const float2*)&red[(size_t)(ww * 32 + q) * RQS + b0e];
                    s.x += p.x; s.y += p.y;
                }
                gv[gate] = s;
            }
            float cA = c_sm[cl * 64 + b0e];
            float cB = c_sm[cl * 64 + b0e + 1];
            cA = sigf(gv[1].x) * cA + sigf(gv[0].x) * tanhfast(gv[2].x);
            cB = sigf(gv[1].y) * cB + sigf(gv[0].y) * tanhfast(gv[2].y);
            float hA = sigf(gv[3].x) * tanhfast(cA);
            float hB = sigf(gv[3].y) * tanhfast(cB);
            c_sm[cl * 64 + b0e]     = cA;
            c_sm[cl * 64 + b0e + 1] = cB;

            out[((size_t)b0e * S_ + t) * H_ + cell] = hA;
            out[((size_t)(b0e + 1) * S_ + t) * H_ + cell] = hB;

            float l0, l1;
            uint32_t hiw = pack_hi(hA, hB, l0, l1);
            uint32_t low = pack_bf2(l0, l1);
            *(uint32_t*)&g_hT_hi[wb][cell * B_ + b0e] = hiw;
            *(uint32_t*)&g_hT_lo[wb][cell * B_ + b0e] = low;
        }

        // distributed grid barrier: arrive at own word, wait on all 8
        __syncthreads();
        if (t < S_ - 1) {
            if (tid == 0) {
                __threadfence();
                atomicAdd(&g_barw[myW][0], 1u);
                const unsigned target = 16u * (unsigned)(t + 1);
                for (;;) {
                    unsigned mn = 0xFFFFFFFFu;
#pragma unroll
                    for (int i = 0; i < NBARW; i++) {
                        unsigned v = ld_acq(&g_barw[i][0]);
                        mn = v < mn ? v : mn;
                    }
                    if (mn >= target) break;
                }
            }
            __syncthreads();
        } else {
            // final step: arrive; CTA 0 waits for everyone then resets
            if (tid == 0) {
                __threadfence();
                atomicAdd(&g_barw[myW][0], 1u);
                if (nt == 0) {
                    const unsigned target = 16u * (unsigned)S_;
                    for (;;) {
                        unsigned mn = 0xFFFFFFFFu;
#pragma unroll
                        for (int i = 0; i < NBARW; i++) {
                            unsigned v = ld_acq(&g_barw[i][0]);
                            mn = v < mn ? v : mn;
                        }
                        if (mn >= target) break;
                    }
#pragma unroll
                    for (int i = 0; i < NBARW; i++) g_barw[i][0] = 0u;
                    __threadfence();
                }
            }
        }
    }
}

// ---------------------------------------------------------------------------
// Launcher
// ---------------------------------------------------------------------------
extern "C" void kernel_launch(void* const* d_in, const int* in_sizes, int n_in,
                              void* d_out, int out_size) {
    const float* features = (const float*)d_in[0];
    const int*   captions = (const int*)  d_in[1];
    const float* W_embed  = (const float*)d_in[2];
    const float* b_embed  = (const float*)d_in[3];
    const float* w_ih     = (const float*)d_in[4];
    const float* w_hh     = (const float*)d_in[5];
    const float* b_ih     = (const float*)d_in[6];
    const float* b_hh     = (const float*)d_in[7];
    const float* h0       = (const float*)d_in[8];
    const float* c0       = (const float*)d_in[9];
    float* out = (float*)d_out;

    cudaFuncSetAttribute(rnn_persistent6,
                         cudaFuncAttributeMaxDynamicSharedMemorySize, SMEM_TOTAL);

    float* pxg;
    cudaGetSymbolAddress((void**)&pxg, g_xg2);

    // prep: packs + state init
    prep_wpack2<<<(PACK2_U32 + 255) / 256, 256>>>(w_hh);
    prep_wih<<<(WIH_U32 + 255) / 256, 256>>>(w_ih);
    build_x_pack<<<(XA_U32 + 255) / 256, 256>>>(features, captions, W_embed, b_embed);
    init_h_kernel<<<(B_ * H_ + 255) / 256, 256>>>(h0);

    // input projection (bias folded, [t][n][b] layout)
    gemm_xg_bf16<<<dim3(M1 / 64, G4 / 128), NTT>>>(b_ih, b_hh, pxg);

    // persistent recurrence (A register-resident, distributed barrier)
    rnn_persistent6<<<NCTA, NTT, SMEM_TOTAL>>>(c0, out);
}

// round 12
// speedup vs baseline: 1.2269x; 1.2269x over previous
#include <cuda_runtime.h>
#include <cuda_bf16.h>
#include <math.h>
#include <stdint.h>

// Problem constants
#define B_  64
#define T_  32
#define S_  33
#define V_  32000
#define E_  512
#define H_  1024
#define G4  4096
#define M1  (S_*B_)       // 2112

// recurrence config (R10, proven)
#define NCTA  128
#define NTT   256         // 8 warps
#define NKS   64
#define CHUNK_ROWS 128
#define NCHUNK (H_/CHUNK_ROWS)   // 8
#define BSROW  144
#define CHUNK_BYTES (CHUNK_ROWS*BSROW)   // 18432
#define NSLOT  4
#define HBUF_BYTES (NSLOT*2*CHUNK_BYTES) // 147456
#define RQS    66
#define SMEM_C_OFF HBUF_BYTES
#define SMEM_TOTAL (HBUF_BYTES + 2048)   // 149504

// xg config: grid (33 t, 8 n-slices); CTA stages x[t] fully in smem
#define XG_MAT_BYTES (512*BSROW)         // 73728
#define XG_SMEM (2*XG_MAT_BYTES)         // 147456

// packs
#define PACK2_U32 (NCTA*2*NKS*32*4)      // w_hh A-frags
#define WA_U32    (256*32*32*4)          // w_ih A-frags: 1,048,576
#define XT_ELEMS  (S_*E_*B_)             // 1,081,344

// ---------------- device scratch ----------------
__device__ float g_xg2[M1 * G4];             // [t][gate*1024+cell][batch]
__device__ uint32_t g_wpA2_hi[PACK2_U32];
__device__ uint32_t g_wpA2_lo[PACK2_U32];
__device__ uint32_t g_wA_hi[WA_U32];
__device__ uint32_t g_wA_lo[WA_U32];
__device__ __nv_bfloat16 g_xT_hi[XT_ELEMS];  // [t][k][batch]
__device__ __nv_bfloat16 g_xT_lo[XT_ELEMS];
__device__ __nv_bfloat16 g_hT_hi[2][H_ * B_];   // double-buffered [cell][batch]
__device__ __nv_bfloat16 g_hT_lo[2][H_ * B_];
__device__ unsigned g_bar;

__device__ __forceinline__ float sigf(float x) {
    return 1.0f / (1.0f + __expf(-x));
}
__device__ __forceinline__ float tanhfast(float x) {
    return 2.0f / (1.0f + __expf(-2.0f * x)) - 1.0f;
}
__device__ __forceinline__ void mma_bf16(float* d, uint32_t a0, uint32_t a1,
                                         uint32_t a2, uint32_t a3,
                                         uint32_t b0, uint32_t b1) {
    asm volatile(
        "mma.sync.aligned.m16n8k16.row.col.f32.bf16.bf16.f32 "
        "{%0,%1,%2,%3}, {%4,%5,%6,%7}, {%8,%9}, {%0,%1,%2,%3};"
        : "+f"(d[0]), "+f"(d[1]), "+f"(d[2]), "+f"(d[3])
        : "r"(a0), "r"(a1), "r"(a2), "r"(a3), "r"(b0), "r"(b1));
}
__device__ __forceinline__ uint32_t pack_hi(float v0, float v1,
                                            float& l0, float& l1) {
    __nv_bfloat16 h0 = __float2bfloat16(v0);
    __nv_bfloat16 h1 = __float2bfloat16(v1);
    l0 = v0 - __bfloat162float(h0);
    l1 = v1 - __bfloat162float(h1);
    return (uint32_t)__bfloat16_as_ushort(h0)
         | ((uint32_t)__bfloat16_as_ushort(h1) << 16);
}
__device__ __forceinline__ uint32_t pack_bf2(float v0, float v1) {
    return (uint32_t)__bfloat16_as_ushort(__float2bfloat16(v0))
         | ((uint32_t)__bfloat16_as_ushort(__float2bfloat16(v1)) << 16);
}
__device__ __forceinline__ uint32_t smem_u32p(const void* p) {
    uint32_t a;
    asm("{ .reg .u64 t; cvta.to.shared.u64 t, %1; cvt.u32.u64 %0, t; }"
        : "=r"(a) : "l"(p));
    return a;
}
__device__ __forceinline__ void cp16(uint32_t sdst, const void* gsrc) {
    asm volatile("cp.async.cg.shared.global [%0], [%1], 16;"
                 :: "r"(sdst), "l"(gsrc) : "memory");
}
__device__ __forceinline__ void ldsm_x2_t(uint32_t& r0, uint32_t& r1,
                                          uint32_t addr) {
    asm volatile("ldmatrix.sync.aligned.m8n8.x2.trans.shared.b16 {%0,%1}, [%2];"
                 : "=r"(r0), "=r"(r1) : "r"(addr));
}

// ---------------------------------------------------------------------------
// 0a) Pack w_hh into A-frag order (rows q = gate*8+cell), proven
// ---------------------------------------------------------------------------
__global__ void prep_wpack2(const float* __restrict__ w_hh) {
    int idx = blockIdx.x * 256 + threadIdx.x;
    if (idx >= PACK2_U32) return;
    int r    = idx & 3;
    int lane = (idx >> 2) & 31;
    int ks   = (idx >> 7) & 63;
    int mi   = (idx >> 13) & 1;
    int nt   = idx >> 14;
    int row16 = (lane >> 2) + ((r & 1) << 3);
    int colp  = (lane & 3) * 2 + ((r >> 1) << 3);
    int q = mi * 16 + row16;
    int gate = q >> 3, cl = q & 7;
    const float* src = w_hh + (size_t)(gate * H_ + nt * 8 + cl) * H_ + ks * 16 + colp;
    float v0 = src[0], v1 = src[1], l0, l1;
    g_wpA2_hi[idx] = pack_hi(v0, v1, l0, l1);
    g_wpA2_lo[idx] = pack_bf2(l0, l1);
}

// 0b) Pack w_ih into A-frag order: [n16tile(256)][ks(32)][lane][r(4)]
__global__ void prep_wA(const float* __restrict__ w_ih) {
    int idx = blockIdx.x * 256 + threadIdx.x;
    if (idx >= WA_U32) return;
    int r     = idx & 3;
    int lane  = (idx >> 2) & 31;
    int ks    = (idx >> 7) & 31;
    int ntile = idx >> 12;
    int row16 = (lane >> 2) + ((r & 1) << 3);
    int colp  = (lane & 3) * 2 + ((r >> 1) << 3);
    int n = ntile * 16 + row16;
    int k = ks * 16 + colp;
    const float* src = w_ih + (size_t)n * E_ + k;
    float v0 = src[0], v1 = src[1], l0, l1;
    g_wA_hi[idx] = pack_hi(v0, v1, l0, l1);
    g_wA_lo[idx] = pack_bf2(l0, l1);
}

// 0c) Build x transposed [t][k][batch] with one-hot gather fused
__global__ void build_xT(const float* __restrict__ features,
                         const int*   __restrict__ captions,
                         const float* __restrict__ W_embed,
                         const float* __restrict__ b_embed) {
    int idx = blockIdx.x * 256 + threadIdx.x;
    if (idx >= XT_ELEMS) return;
    int b = idx & 63;
    int k = (idx >> 6) & 511;
    int t = idx >> 15;
    float v;
    if (t == 0) v = features[b * E_ + k];
    else {
        int cap = captions[b * T_ + (t - 1)];
        v = W_embed[(size_t)k * V_ + cap] + b_embed[k];
    }
    __nv_bfloat16 hi = __float2bfloat16(v);
    g_xT_hi[idx] = hi;
    g_xT_lo[idx] = __float2bfloat16(v - __bfloat162float(hi));
}

// 0d) Init h buf 0, transposed [cell][batch]
__global__ void init_h_kernel(const float* __restrict__ h0) {
    int idx = blockIdx.x * 256 + threadIdx.x;
    if (idx >= B_ * H_) return;
    int cell = idx >> 6;
    int b    = idx & 63;
    float v = h0[b * H_ + cell];
    __nv_bfloat16 hi = __float2bfloat16(v);
    g_hT_hi[0][idx] = hi;
    g_hT_lo[0][idx] = __float2bfloat16(v - __bfloat162float(hi));
}

// ---------------------------------------------------------------------------
// 1) xg v2: CTA (t, slice) stages x[t] in smem once; warps stream w_ih frags,
//    reusing each B-frag across 4 m16-tiles. Output xg2[t][n][b] + bias.
// ---------------------------------------------------------------------------
__global__ __launch_bounds__(NTT, 1)
void gemm_xg3(const float* __restrict__ b_ih,
              const float* __restrict__ b_hh,
              float* __restrict__ C) {
    extern __shared__ char smem[];
    const uint32_t sbase = smem_u32p(smem);

    const int tid  = threadIdx.x;
    const int lane = tid & 31;
    const int wi   = tid >> 5;          // warp -> 4 m16 tiles
    const int t    = blockIdx.x;
    const int s    = blockIdx.y;        // n-slice (512 rows)
    const int g    = lane >> 2;
    const int tig  = lane & 3;

    // stage x[t]: 512 k-rows x 64 b, hi+lo (144B padded rows)
#pragma unroll
    for (int i = 0; i < 32; i++) {
        int lin = i * NTT + tid;        // 0..8191
        int mat = lin >> 12;
        int within = lin & 4095;
        int r = within >> 3;
        int col = within & 7;
        const uint4* gsrc = ((const uint4*)(mat ? g_xT_lo : g_xT_hi))
                            + ((size_t)t * 512 + r) * 8 + col;
        cp16(sbase + mat * XG_MAT_BYTES + r * BSROW + col * 16, gsrc);
    }
    asm volatile("cp.async.commit_group;" ::: "memory");
    asm volatile("cp.async.wait_group 0;" ::: "memory");
    __syncthreads();

    float acc[4][8][4];
#pragma unroll
    for (int i = 0; i < 4; i++)
#pragma unroll
        for (int j = 0; j < 8; j++)
#pragma unroll
            for (int c = 0; c < 4; c++) acc[i][j][c] = 0.0f;

    const uint4* aH = (const uint4*)g_wA_hi;
    const uint4* aL = (const uint4*)g_wA_lo;
    const int ntile0 = s * 32 + wi * 4;

    for (int ks = 0; ks < 32; ks++) {
        // B frags once per ks (shared by all 4 tiles)
        const uint32_t rowAddr = sbase + (uint32_t)((ks * 16 + (lane & 15)) * BSROW);
        uint32_t bh[8][2], bl[8][2];
#pragma unroll
        for (int j = 0; j < 8; j++) {
            ldsm_x2_t(bh[j][0], bh[j][1], rowAddr + j * 16);
            ldsm_x2_t(bl[j][0], bl[j][1], rowAddr + XG_MAT_BYTES + j * 16);
        }
#pragma unroll
        for (int i = 0; i < 4; i++) {
            size_t ai = ((size_t)(ntile0 + i) * 32 + ks) * 32 + lane;
            uint4 ah = __ldg(&aH[ai]);
            uint4 al = __ldg(&aL[ai]);
#pragma unroll
            for (int j = 0; j < 8; j++) {
                mma_bf16(acc[i][j], ah.x, ah.y, ah.z, ah.w, bh[j][0], bh[j][1]);
                mma_bf16(acc[i][j], ah.x, ah.y, ah.z, ah.w, bl[j][0], bl[j][1]);
                mma_bf16(acc[i][j], al.x, al.y, al.z, al.w, bh[j][0], bh[j][1]);
            }
        }
    }

    // epilogue: add bias, write xg2[(t*4096 + n)*64 + b]
#pragma unroll
    for (int i = 0; i < 4; i++) {
        int n0 = (ntile0 + i) * 16 + g;
        int n1 = n0 + 8;
        float bx0 = b_ih[n0] + b_hh[n0];
        float bx1 = b_ih[n1] + b_hh[n1];
#pragma unroll
        for (int j = 0; j < 8; j++) {
            int b = j * 8 + tig * 2;
            *(float2*)&C[((size_t)t * G4 + n0) * 64 + b] =
                make_float2(acc[i][j][0] + bx0, acc[i][j][1] + bx0);
            *(float2*)&C[((size_t)t * G4 + n1) * 64 + b] =
                make_float2(acc[i][j][2] + bx1, acc[i][j][3] + bx1);
        }
    }
}

// ---------------------------------------------------------------------------
// helper: stage one 128-row chunk (hi+lo) into smem slot via cp.async
// ---------------------------------------------------------------------------
__device__ __forceinline__ void stage_chunk(uint32_t sbase, int slot,
                                            const __nv_bfloat16* hi,
                                            const __nv_bfloat16* lo,
                                            int c, int tid) {
#pragma unroll
    for (int i = 0; i < 8; i++) {
        int lin = i * NTT + tid;
        int mat = lin >> 10;
        int within = lin & 1023;
        int row = within >> 3;
        int col = within & 7;
        const uint4* gsrc = ((const uint4*)(mat ? lo : hi))
            + (size_t)(c * CHUNK_ROWS + row) * 8 + col;
        cp16(sbase + (slot * 2 + mat) * CHUNK_BYTES + row * BSROW + col * 16,
             gsrc);
    }
    asm volatile("cp.async.commit_group;" ::: "memory");
}

// ---------------------------------------------------------------------------
// 2) Persistent recurrence (R10 proven: A register-resident, 4-slot staging,
//    double-buffered h, single-counter monotone barrier).
// ---------------------------------------------------------------------------
__global__ __launch_bounds__(NTT, 1)
void rnn_persistent5(const float* __restrict__ c0,
                     float* __restrict__ out) {
    extern __shared__ char smem[];
    const uint32_t sbase = smem_u32p(smem);
    float* red  = (float*)smem;                      // overlays staging slots
    float* c_sm = (float*)(smem + SMEM_C_OFF);

    const int tid  = threadIdx.x;
    const int lane = tid & 31;
    const int w    = tid >> 5;          // warp owns ks = 8c + w
    const int nt   = blockIdx.x;
    const int g    = lane >> 2;
    const int tig  = lane & 3;

    // ---- load ALL A fragments into registers (reused for all 33 steps) ----
    uint4 aH0r[NCHUNK], aH1r[NCHUNK], aL0r[NCHUNK], aL1r[NCHUNK];
    {
        const uint4* aH0 = (const uint4*)g_wpA2_hi + ((size_t)(nt * 2 + 0) * NKS) * 32 + lane;
        const uint4* aH1 = (const uint4*)g_wpA2_hi + ((size_t)(nt * 2 + 1) * NKS) * 32 + lane;
        const uint4* aL0 = (const uint4*)g_wpA2_lo + ((size_t)(nt * 2 + 0) * NKS) * 32 + lane;
        const uint4* aL1 = (const uint4*)g_wpA2_lo + ((size_t)(nt * 2 + 1) * NKS) * 32 + lane;
#pragma unroll
        for (int c = 0; c < NCHUNK; c++) {
            int ks = c * 8 + w;
            aH0r[c] = __ldg(aH0 + (size_t)ks * 32);
            aH1r[c] = __ldg(aH1 + (size_t)ks * 32);
            aL0r[c] = __ldg(aL0 + (size_t)ks * 32);
            aL1r[c] = __ldg(aL1 + (size_t)ks * 32);
        }
    }

    const uint32_t lmRow = (uint32_t)((w * 16 + (lane & 15)) * BSROW);

    const int cl  = tid >> 5;
    const int b0e = (tid & 31) * 2;
    const int cell = nt * 8 + cl;

    c_sm[cl * 64 + b0e]     = c0[b0e * H_ + cell];
    c_sm[cl * 64 + b0e + 1] = c0[(b0e + 1) * H_ + cell];
    __syncthreads();

    for (int t = 0; t < S_; t++) {
        const int rb = t & 1;
        const int wb = (t + 1) & 1;
        const __nv_bfloat16* hiSrc = g_hT_hi[rb];
        const __nv_bfloat16* loSrc = g_hT_lo[rb];

        // prologue: stage chunks 0,1 immediately
        stage_chunk(sbase, 0, hiSrc, loSrc, 0, tid);
        stage_chunk(sbase, 1, hiSrc, loSrc, 1, tid);

        // prefetch xg gate values (off the critical path)
        float2 xp[4];
#pragma unroll
        for (int gate = 0; gate < 4; gate++)
            xp[gate] = __ldg((const float2*)
                &g_xg2[((size_t)t * G4 + gate * H_ + cell) * 64 + b0e]);

        float acc[2][NCHUNK][4];
#pragma unroll
        for (int i = 0; i < 2; i++)
#pragma unroll
            for (int j = 0; j < NCHUNK; j++)
#pragma unroll
                for (int c = 0; c < 4; c++) acc[i][j][c] = 0.0f;

#pragma unroll
        for (int c = 0; c < NCHUNK; c++) {
            if (c + 2 < NCHUNK)
                stage_chunk(sbase, (c + 2) & 3, hiSrc, loSrc, c + 2, tid);
            if (c < NCHUNK - 2)
                asm volatile("cp.async.wait_group 2;" ::: "memory");
            else if (c == NCHUNK - 2)
                asm volatile("cp.async.wait_group 1;" ::: "memory");
            else
                asm volatile("cp.async.wait_group 0;" ::: "memory");
            __syncthreads();   // single sync per chunk (slot reuse distance 4)

            const int slot = c & 3;
            const uint32_t bHbase = sbase + (slot * 2 + 0) * CHUNK_BYTES + lmRow;
            const uint32_t bLbase = sbase + (slot * 2 + 1) * CHUNK_BYTES + lmRow;

            uint32_t bh[8][2], bl[8][2];
#pragma unroll
            for (int j = 0; j < 8; j++) {
                ldsm_x2_t(bh[j][0], bh[j][1], bHbase + j * 16);
                ldsm_x2_t(bl[j][0], bl[j][1], bLbase + j * 16);
            }
#pragma unroll
            for (int j = 0; j < 8; j++) {
                mma_bf16(acc[0][j], aH0r[c].x, aH0r[c].y, aH0r[c].z, aH0r[c].w,
                         bh[j][0], bh[j][1]);
                mma_bf16(acc[1][j], aH1r[c].x, aH1r[c].y, aH1r[c].z, aH1r[c].w,
                         bh[j][0], bh[j][1]);
                mma_bf16(acc[0][j], aH0r[c].x, aH0r[c].y, aH0r[c].z, aH0r[c].w,
                         bl[j][0], bl[j][1]);
                mma_bf16(acc[1][j], aH1r[c].x, aH1r[c].y, aH1r[c].z, aH1r[c].w,
                         bl[j][0], bl[j][1]);
                mma_bf16(acc[0][j], aL0r[c].x, aL0r[c].y, aL0r[c].z, aL0r[c].w,
                         bh[j][0], bh[j][1]);
                mma_bf16(acc[1][j], aL1r[c].x, aL1r[c].y, aL1r[c].z, aL1r[c].w,
                         bh[j][0], bh[j][1]);
            }
        }
        __syncthreads();   // all ldsm reads done before red overlays slots

        // cross-warp reduce (overlays staging slots)
#pragma unroll
        for (int mi = 0; mi < 2; mi++) {
            int q = mi * 16 + g;
#pragma unroll
            for (int j = 0; j < 8; j++) {
                int col = j * 8 + tig * 2;
                *(float2*)&red[(size_t)(w * 32 + q) * RQS + col] =
                    make_float2(acc[mi][j][0], acc[mi][j][1]);
                *(float2*)&red[(size_t)(w * 32 + q + 8) * RQS + col] =
                    make_float2(acc[mi][j][2], acc[mi][j][3]);
            }
        }
        __syncthreads();

        // fused LSTM epilogue
        {
            float2 gv[4];
#pragma unroll
            for (int gate = 0; gate < 4; gate++) {
                int q = gate * 8 + cl;
                float2 s = xp[gate];
#pragma unroll
                for (int ww = 0; ww < 8; ww++) {
                    float2 p = *(const float2*)&red[(size_t)(ww * 32 + q) * RQS + b0e];
                    s.x += p.x; s.y += p.y;
                }
                gv[gate] = s;
            }
            float cA = c_sm[cl * 64 + b0e];
            float cB = c_sm[cl * 64 + b0e + 1];
            cA = sigf(gv[1].x) * cA + sigf(gv[0].x) * tanhfast(gv[2].x);
            cB = sigf(gv[1].y) * cB + sigf(gv[0].y) * tanhfast(gv[2].y);
            float hA = sigf(gv[3].x) * tanhfast(cA);
            float hB = sigf(gv[3].y) * tanhfast(cB);
            c_sm[cl * 64 + b0e]     = cA;
            c_sm[cl * 64 + b0e + 1] = cB;

            out[((size_t)b0e * S_ + t) * H_ + cell] = hA;
            out[((size_t)(b0e + 1) * S_ + t) * H_ + cell] = hB;

            float l0, l1;
            uint32_t hiw = pack_hi(hA, hB, l0, l1);
            uint32_t low = pack_bf2(l0, l1);
            *(uint32_t*)&g_hT_hi[wb][cell * B_ + b0e] = hiw;
            *(uint32_t*)&g_hT_lo[wb][cell * B_ + b0e] = low;
        }

        // grid barrier (proven R10 monotone scheme — single counter)
        __syncthreads();
        if (t < S_ - 1) {
            if (tid == 0) {
                __threadfence();
                atomicAdd(&g_bar, 1u);
                unsigned target = (unsigned)NCTA * (t + 1);
                unsigned v;
                do {
                    asm volatile("ld.global.acquire.gpu.u32 %0, [%1];"
                                 : "=r"(v) : "l"(&g_bar));
                } while (v < target);
            }
            __syncthreads();
        } else {
            if (tid == 0) {
                __threadfence();
                unsigned old = atomicAdd(&g_bar, 1u);
                if (old == (unsigned)NCTA * S_ - 1u)
                    atomicExch(&g_bar, 0u);   // reset for graph replay
            }
        }
    }
}

// ---------------------------------------------------------------------------
// Launcher
// ---------------------------------------------------------------------------
extern "C" void kernel_launch(void* const* d_in, const int* in_sizes, int n_in,
                              void* d_out, int out_size) {
    const float* features = (const float*)d_in[0];
    const int*   captions = (const int*)  d_in[1];
    const float* W_embed  = (const float*)d_in[2];
    const float* b_embed  = (const float*)d_in[3];
    const float* w_ih     = (const float*)d_in[4];
    const float* w_hh     = (const float*)d_in[5];
    const float* b_ih     = (const float*)d_in[6];
    const float* b_hh     = (const float*)d_in[7];
    const float* h0       = (const float*)d_in[8];
    const float* c0       = (const float*)d_in[9];
    float* out = (float*)d_out;

    cudaFuncSetAttribute(rnn_persistent5,
                         cudaFuncAttributeMaxDynamicSharedMemorySize, SMEM_TOTAL);
    cudaFuncSetAttribute(gemm_xg3,
                         cudaFuncAttributeMaxDynamicSharedMemorySize, XG_SMEM);

    float* pxg;
    cudaGetSymbolAddress((void**)&pxg, g_xg2);

    // prep: packs + state init
    prep_wpack2<<<(PACK2_U32 + 255) / 256, 256>>>(w_hh);
    prep_wA<<<(WA_U32 + 255) / 256, 256>>>(w_ih);
    build_xT<<<(XT_ELEMS + 255) / 256, 256>>>(features, captions, W_embed, b_embed);
    init_h_kernel<<<(B_ * H_ + 255) / 256, 256>>>(h0);

    // input projection (L2-lean: smem-staged x, B-frag reuse across tiles)
    gemm_xg3<<<dim3(S_, 8), NTT, XG_SMEM>>>(b_ih, b_hh, pxg);

    // persistent recurrence (R10 proven)
    rnn_persistent5<<<NCTA, NTT, SMEM_TOTAL>>>(c0, out);
}